// round 13
// baseline (speedup 1.0000x reference)
#include <cuda_runtime.h>
#include <math_constants.h>
#include <cooperative_groups.h>

namespace cg = cooperative_groups;

#define Bn 128
#define Tn 512
#define Kn 256
#define HB 64   // clusters in k1; cluster c owns batches (c, c+HB)

// ---------------- scratch (static device globals; no allocation allowed) ----
__device__ float  g_transT[Kn * Kn];             // trans transposed: [j][i]
__device__ float  g_av[(size_t)Bn * Tn * Kn];    // Viterbi alphas (64 MiB)
__device__ float  g_logZ[Bn];
__device__ float  g_score[Bn];
__device__ int    g_best[Bn];
__device__ int    g_pred[Bn * Tn];

// ---------------- K0: transposed trans (for k4 backtrace) ---------------------
__global__ void k0_prep(const float* __restrict__ trans) {
    int idx = blockIdx.x * blockDim.x + threadIdx.x;
    if (idx < Kn * Kn) {
        int i = idx >> 8, j = idx & 255;
        g_transT[j * Kn + i] = trans[idx];
    }
}

// ---------------- K1: clustered forward(logZ) + Viterbi max scan --------------
// 2-CTA cluster per batch pair (b0=c, b1=c+HB). CTA rank r owns output columns
// j in [r*128, r*128+128) -> its T slice is 128KB and stays L1-resident; the
// hot loop reads raw fp32 trans via __ldg (L1 hit) and computes exp inline
// (bit-identical to precomputed __expf values). Per step the 2 KB of (af, av)
// state is exchanged via DSMEM (double-buffered) with ONE cluster.sync.
// Thread (jl, h): jl=tid&127 output col, h=tid>>7 owns source rows
// [h*64, h*64+64). No argmax in the hot loop; av stored to g_av (__stcg).
__global__ void __cluster_dims__(2, 1, 1) __launch_bounds__(512, 1) k1_scan(
    const float* __restrict__ logit,
    const float* __restrict__ trans,
    const float* __restrict__ startv,
    const float* __restrict__ endv,
    const int*   __restrict__ seq_lens)
{
    cg::cluster_group cl = cg::this_cluster();
    const unsigned r = cl.block_rank();           // 0 or 1

    int cid = blockIdx.x >> 1;
    int b0 = cid, b1 = cid + HB;
    int tid = threadIdx.x;
    int jl = tid & 127;
    int h = tid >> 7;                             // 0..3
    int j = (int)r * 128 + jl;                    // global output column
    int lane = tid & 31, w = tid >> 5;            // warps 0..15

    __shared__ float4 s_afav[2][Kn];   // parity-buffered (af0, av0, af1, av1), all i
    __shared__ float4 s_pva[Kn];       // (p0, av0, p1, av1), all i
    __shared__ float4 s_part[3][128];  // h=1..3 partials (s0, s1, bv0, bv1)
    __shared__ float  red0[8], red1[8];

    float4* peer_afav = (float4*)cl.map_shared_rank(&s_afav[0][0], r ^ 1);

    int L0 = seq_lens[b0];
    int L1 = seq_lens[b1];
    int Lmax = max(L0, L1);

    const float* em0 = logit + (size_t)b0 * Tn * Kn;
    const float* em1 = logit + (size_t)b1 * Tn * Kn;
    float* avg0 = g_av + (size_t)b0 * Tn * Kn;
    float* avg1 = g_av + (size_t)b1 * Tn * Kn;

    float af0 = 0.f, av0 = 0.f, af1 = 0.f, av1 = 0.f;
    if (h == 0) {
        float sv = startv[j];
        af0 = sv + __ldcg(em0 + j); av0 = af0;
        af1 = sv + __ldcg(em1 + j); av1 = af1;
        __stcg(avg0 + j, av0);                 // av at t=0 (backtrace needs it)
        __stcg(avg1 + j, av1);
    }

    // column j of trans, rows h*64 .. h*64+63  (L1-resident after step 1)
    const float* Tp = trans + j + (size_t)(h * 64) * Kn;

    for (int t = 1; t < Lmax; ++t) {
        int p = t & 1;
        bool act0 = t < L0, act1 = t < L1;

        float e0 = 0.f, e1 = 0.f;
        if (h == 0) {
            e0 = __ldcg(em0 + t * Kn + j);     // streaming: keep out of L1
            e1 = __ldcg(em1 + t * Kn + j);
            float4 st4 = make_float4(af0, av0, af1, av1);
            s_afav[p][j] = st4;                 // own half, local
            peer_afav[p * Kn + j] = st4;        // own half -> peer's smem
        }
        cl.sync();                               // exchange + full ordering

        // ---- global max over all 256 forward alphas (both batches) ----
        if (tid < 256) {
            float4 a = s_afav[p][tid];
            float x0 = a.x, x1 = a.z;
            #pragma unroll
            for (int o = 16; o; o >>= 1) {
                x0 = fmaxf(x0, __shfl_xor_sync(0xffffffffu, x0, o));
                x1 = fmaxf(x1, __shfl_xor_sync(0xffffffffu, x1, o));
            }
            if (lane == 0) { red0[w] = x0; red1[w] = x1; }
        }
        __syncthreads();
        float m0 = fmaxf(fmaxf(fmaxf(red0[0], red0[1]), fmaxf(red0[2], red0[3])),
                         fmaxf(fmaxf(red0[4], red0[5]), fmaxf(red0[6], red0[7])));
        float m1 = fmaxf(fmaxf(fmaxf(red1[0], red1[1]), fmaxf(red1[2], red1[3])),
                         fmaxf(fmaxf(red1[4], red1[5]), fmaxf(red1[6], red1[7])));
        if (tid < 256) {
            float4 a = s_afav[p][tid];
            s_pva[tid] = make_float4(__expf(a.x - m0), a.y, __expf(a.z - m1), a.w);
        }
        __syncthreads();

        // ---- inner quarter-K: 64 rows, L1-hit T loads + inline exp ----
        float s0 = 0.f, s1 = 0.f;
        float bv0 = -CUDART_INF_F, bv1 = -CUDART_INF_F;

        const float4* pv_ptr = s_pva + h * 64;

        #pragma unroll 16
        for (int i = 0; i < 64; ++i) {
            float tv = __ldg(Tp + i * Kn);       // L1 hit after first step
            float4 pv = pv_ptr[i];
            float e = __expf(tv);                // == precomputed __expf(t)
            s0 += pv.x * e;
            s1 += pv.z * e;
            bv0 = fmaxf(bv0, pv.y + tv);         // exact fp32 add + exact max
            bv1 = fmaxf(bv1, pv.w + tv);
        }

        if (h) s_part[h - 1][jl] = make_float4(s0, s1, bv0, bv1);
        __syncthreads();

        if (h == 0) {
            #pragma unroll
            for (int q = 0; q < 3; ++q) {
                float4 ps = s_part[q][jl];
                s0 += ps.x;
                s1 += ps.y;
                bv0 = fmaxf(bv0, ps.z);
                bv1 = fmaxf(bv1, ps.w);
            }
            if (act0) {
                af0 = m0 + __logf(s0) + e0;
                av0 = bv0 + e0;
                __stcg(avg0 + t * Kn + j, av0);
            }
            if (act1) {
                af1 = m1 + __logf(s1) + e1;
                av1 = bv1 + e1;
                __stcg(avg1 + t * Kn + j, av1);
            }
        }
        // next step's cl.sync orders these updates vs peer reads
    }

    // ---- epilogue: exchange (af+end, av+end); rank 0 reduces ----
    int pe = Lmax & 1;
    if (h == 0) {
        float ev = endv[j];
        float4 st4 = make_float4(af0 + ev, av0 + ev, af1 + ev, av1 + ev);
        s_afav[pe][j] = st4;
        peer_afav[pe * Kn + j] = st4;
    }
    cl.sync();

    if (r == 0) {
        // logZ = logsumexp over 256 z-values, both batches
        float z0 = 0.f, z1 = 0.f;
        if (tid < 256) {
            float4 a = s_afav[pe][tid];
            z0 = a.x; z1 = a.z;
            float x0 = z0, x1 = z1;
            #pragma unroll
            for (int o = 16; o; o >>= 1) {
                x0 = fmaxf(x0, __shfl_xor_sync(0xffffffffu, x0, o));
                x1 = fmaxf(x1, __shfl_xor_sync(0xffffffffu, x1, o));
            }
            if (lane == 0) { red0[w] = x0; red1[w] = x1; }
        }
        __syncthreads();
        float m0 = fmaxf(fmaxf(fmaxf(red0[0], red0[1]), fmaxf(red0[2], red0[3])),
                         fmaxf(fmaxf(red0[4], red0[5]), fmaxf(red0[6], red0[7])));
        float m1 = fmaxf(fmaxf(fmaxf(red1[0], red1[1]), fmaxf(red1[2], red1[3])),
                         fmaxf(fmaxf(red1[4], red1[5]), fmaxf(red1[6], red1[7])));
        __syncthreads();
        if (tid < 256) {
            float ex0 = __expf(z0 - m0);
            float ex1 = __expf(z1 - m1);
            #pragma unroll
            for (int o = 16; o; o >>= 1) {
                ex0 += __shfl_xor_sync(0xffffffffu, ex0, o);
                ex1 += __shfl_xor_sync(0xffffffffu, ex1, o);
            }
            if (lane == 0) { red0[w] = ex0; red1[w] = ex1; }
        }
        __syncthreads();
        if (tid == 0) {
            float ss0 = red0[0] + red0[1] + red0[2] + red0[3]
                      + red0[4] + red0[5] + red0[6] + red0[7];
            float ss1 = red1[0] + red1[1] + red1[2] + red1[3]
                      + red1[4] + red1[5] + red1[6] + red1[7];
            g_logZ[b0] = m0 + __logf(ss0);
            g_logZ[b1] = m1 + __logf(ss1);
            // best_last: first argmax, exact ascending linear scan
            float bv = s_afav[pe][0].y; int bi = 0;
            float bw = s_afav[pe][0].w; int bj = 0;
            for (int i = 1; i < Kn; ++i) {
                float v = s_afav[pe][i].y;
                float u = s_afav[pe][i].w;
                if (v > bv) { bv = v; bi = i; }
                if (u > bw) { bw = u; bj = i; }
            }
            g_best[b0] = bi;
            g_best[b1] = bj;
        }
    }
}

// ---------------- K2: gold-path score per batch ------------------------------
__global__ void k2_score(
    const float* __restrict__ logit,
    const float* __restrict__ trans,
    const float* __restrict__ startv,
    const float* __restrict__ endv,
    const int*   __restrict__ target,
    const int*   __restrict__ seq_lens)
{
    int b = blockIdx.x, tid = threadIdx.x;
    int L = seq_lens[b];
    const int*   tg = target + b * Tn;
    const float* em = logit + (size_t)b * Tn * Kn;

    float part = 0.f;
    for (int t = 1 + tid; t < L; t += blockDim.x) {
        int cur = tg[t], prev = tg[t - 1];
        part += trans[prev * Kn + cur] + em[t * Kn + cur];
    }
    #pragma unroll
    for (int o = 16; o; o >>= 1) part += __shfl_xor_sync(0xffffffffu, part, o);
    __shared__ float red[4];
    if ((tid & 31) == 0) red[tid >> 5] = part;
    __syncthreads();
    if (tid == 0) {
        float s = red[0] + red[1] + red[2] + red[3];
        int t0 = tg[0];
        s += startv[t0] + em[t0];
        s += endv[tg[L - 1]];
        g_score[b] = s;
    }
}

// ---------------- K3: loss = mean(logZ - score) ------------------------------
__global__ void k3_loss(float* __restrict__ out) {
    int b = threadIdx.x;  // 128 threads
    float v = g_logZ[b] - g_score[b];
    #pragma unroll
    for (int o = 16; o; o >>= 1) v += __shfl_xor_sync(0xffffffffu, v, o);
    __shared__ float red[4];
    if ((b & 31) == 0) red[b >> 5] = v;
    __syncthreads();
    if (b == 0) out[0] = (red[0] + red[1] + red[2] + red[3]) / (float)Bn;
}

// ---------------- K4: backtrace with on-the-fly backpointer recompute --------
// One warp per batch. bp[t][tag] = argmax_i(av[t-1][i] + trans[i][tag]) is
// recomputed exactly: same fp32 adds, first-index tie-break (per-lane
// ascending i with strict >, cross-lane min-index on equal values).
__global__ void k4_backtrace(const int* __restrict__ seq_lens,
                             float* __restrict__ out_pred)
{
    int b = blockIdx.x;
    int lane = threadIdx.x;
    int L = seq_lens[b];
    int tag = g_best[b];
    const float* avb = g_av + (size_t)b * Tn * Kn;

    if (lane == 0) {
        g_pred[b * Tn + Tn - 1] = tag;
        out_pred[b * Tn + Tn - 1] = (float)tag;
    }

    // prefetch av row for the first active step
    float avr[8];
    {
        const float* row = avb + (size_t)(min(L, Tn) - 2) * Kn;  // t-1 for t=L-1
        #pragma unroll
        for (int k = 0; k < 8; ++k) avr[k] = __ldcg(row + k * 32 + lane);
    }

    for (int s = Tn - 2; s >= 0; --s) {
        int t = s + 1;
        if (t < L) {
            const float* trow = g_transT + tag * Kn;
            float bv = -CUDART_INF_F; int bi = 0;
            #pragma unroll
            for (int k = 0; k < 8; ++k) {
                float v = avr[k] + __ldg(trow + k * 32 + lane);
                if (v > bv) { bv = v; bi = k * 32 + lane; }   // ascending i: first
            }
            // prefetch next av row (independent of the reduce below)
            if (t - 2 >= 0) {
                const float* row = avb + (size_t)(t - 2) * Kn;
                #pragma unroll
                for (int k = 0; k < 8; ++k) avr[k] = __ldcg(row + k * 32 + lane);
            }
            // cross-lane argmax, min-index tie-break
            #pragma unroll
            for (int o = 16; o; o >>= 1) {
                float ov = __shfl_xor_sync(0xffffffffu, bv, o);
                int   oi = __shfl_xor_sync(0xffffffffu, bi, o);
                if (ov > bv || (ov == bv && oi < bi)) { bv = ov; bi = oi; }
            }
            tag = bi;
        }
        if (lane == 0) {
            g_pred[b * Tn + s] = tag;
            out_pred[b * Tn + s] = (float)tag;
        }
    }
}

// ---------------- K5: rearrange + log_softmax --------------------------------
__global__ __launch_bounds__(Kn) void k5_logits(
    const float* __restrict__ logit,
    float* __restrict__ out_lp)
{
    int row = blockIdx.x;   // b*T + t
    int j = threadIdx.x;
    int lane = j & 31, w = j >> 5;

    const float* x = logit + (size_t)row * Kn;
    float xv = x[j];

    __shared__ float sh[Kn];
    __shared__ float redv[8];
    __shared__ int   redi[8];
    sh[j] = xv;

    // argmax with first-index tie-break (exact jnp.argmax semantics)
    float bv = xv; int bi = j;
    #pragma unroll
    for (int o = 16; o; o >>= 1) {
        float ov = __shfl_xor_sync(0xffffffffu, bv, o);
        int   oi = __shfl_xor_sync(0xffffffffu, bi, o);
        if (ov > bv || (ov == bv && oi < bi)) { bv = ov; bi = oi; }
    }
    if (lane == 0) { redv[w] = bv; redi[w] = bi; }
    __syncthreads();
    float mv = redv[0]; int mi = redi[0];
    #pragma unroll
    for (int k = 1; k < 8; ++k) {
        float ov = redv[k]; int oi = redi[k];
        if (ov > mv || (ov == mv && oi < mi)) { mv = ov; mi = oi; }
    }

    int p = g_pred[row];
    float labv = sh[p];

    float y = xv;
    if (j == p)  y = mv;     // out.at[pred].set(maxv)
    if (j == mi) y = labv;   // out.at[argm].set(labv)  (applied second, as in ref)

    // log_softmax: max of rearranged array == mv (value multiset preserved)
    float ex = __expf(y - mv);
    #pragma unroll
    for (int o = 16; o; o >>= 1) ex += __shfl_xor_sync(0xffffffffu, ex, o);
    __syncthreads();
    if (lane == 0) redv[w] = ex;
    __syncthreads();
    float ssum = redv[0] + redv[1] + redv[2] + redv[3]
               + redv[4] + redv[5] + redv[6] + redv[7];
    out_lp[(size_t)row * Kn + j] = y - mv - __logf(ssum);
}

// ---------------- launch ------------------------------------------------------
extern "C" void kernel_launch(void* const* d_in, const int* in_sizes, int n_in,
                              void* d_out, int out_size)
{
    (void)in_sizes; (void)n_in; (void)out_size;
    const float* logit  = (const float*)d_in[0];   // [B,T,K] f32
    const float* trans  = (const float*)d_in[1];   // [K,K]   f32
    const float* startv = (const float*)d_in[2];   // [K]     f32
    const float* endv   = (const float*)d_in[3];   // [K]     f32
    const int*   target = (const int*)d_in[4];     // [B,T]   i32
    const int*   seqlen = (const int*)d_in[5];     // [B]     i32

    float* out      = (float*)d_out;
    float* out_pred = out + 1;              // [B,T]   (pred cast to f32)
    float* out_lp   = out + 1 + Bn * Tn;    // [B,T,K]

    k0_prep<<<(Kn * Kn + 255) / 256, 256>>>(trans);
    k1_scan<<<2 * HB, 512>>>(logit, trans, startv, endv, seqlen);  // 64 clusters x 2
    k2_score<<<Bn, 128>>>(logit, trans, startv, endv, target, seqlen);
    k3_loss<<<1, 128>>>(out);
    k4_backtrace<<<Bn, 32>>>(seqlen, out_pred);
    k5_logits<<<Bn * Tn, Kn>>>(logit, out_lp);
}

// round 14
// speedup vs baseline: 1.2825x; 1.2825x over previous
#include <cuda_runtime.h>
#include <math_constants.h>
#include <cooperative_groups.h>

namespace cg = cooperative_groups;

#define Bn 128
#define Tn 512
#define Kn 256
#define HB 64   // clusters in k1; cluster c owns batches (c, c+HB)

// ---------------- scratch (static device globals; no allocation allowed) ----
__device__ float  g_transT[Kn * Kn];             // trans transposed: [j][i]
__device__ float  g_av[(size_t)Bn * Tn * Kn];    // Viterbi alphas (64 MiB)
__device__ float  g_logZ[Bn];
__device__ float  g_score[Bn];
__device__ int    g_best[Bn];
__device__ int    g_pred[Bn * Tn];

// ---------------- K0: transposed trans (for k4 backtrace) ---------------------
__global__ void k0_prep(const float* __restrict__ trans) {
    int idx = blockIdx.x * blockDim.x + threadIdx.x;
    if (idx < Kn * Kn) {
        int i = idx >> 8, j = idx & 255;
        g_transT[j * Kn + i] = trans[idx];
    }
}

// ---------------- K1: clustered forward(logZ) + Viterbi max scan --------------
// 2-CTA cluster per batch pair (b0=c, b1=c+HB). CTA rank r owns output columns
// j in [r*128, r*128+128). The 128KB T slice is staged in DYNAMIC SMEM once
// (no L1 set-conflict thrash, no per-step L2 stream); exp computed inline
// (bit-identical to precomputed __expf). Stabilizer m = alpha[0] (any common
// m is mathematically valid; spread << fp32 exp range) -> no max reduction on
// the critical path. Per step: ONE cluster.sync + 2 __syncthreads.
// Thread (jl, h): jl=tid&127 output col, h=tid>>7 owns source rows
// [h*64, h*64+64). No argmax in the hot loop; av stored exactly to g_av.
__global__ void __cluster_dims__(2, 1, 1) __launch_bounds__(512, 1) k1_scan(
    const float* __restrict__ logit,
    const float* __restrict__ trans,
    const float* __restrict__ startv,
    const float* __restrict__ endv,
    const int*   __restrict__ seq_lens)
{
    cg::cluster_group cl = cg::this_cluster();
    const unsigned r = cl.block_rank();           // 0 or 1

    int cid = blockIdx.x >> 1;
    int b0 = cid, b1 = cid + HB;
    int tid = threadIdx.x;
    int jl = tid & 127;
    int h = tid >> 7;                             // 0..3
    int j = (int)r * 128 + jl;                    // global output column
    int lane = tid & 31, w = tid >> 5;            // warps 0..15

    extern __shared__ float s_T[];     // [256 rows][128 cols] = 128 KB, this CTA's slice

    __shared__ float4 s_afav[2][Kn];   // parity-buffered (af0, av0, af1, av1), all i
    __shared__ float4 s_pva[Kn];       // (p0, av0, p1, av1), all i
    __shared__ float4 s_part[3][128];  // h=1..3 partials (s0, s1, bv0, bv1)
    __shared__ float  red0[8], red1[8];

    float4* peer_afav = (float4*)cl.map_shared_rank(&s_afav[0][0], r ^ 1);

    // ---- one-time: stage this CTA's T slice into smem (coalesced) ----
    for (int idx = tid; idx < Kn * 128; idx += 512) {
        int i = idx >> 7, jj = idx & 127;
        s_T[idx] = trans[i * Kn + (int)r * 128 + jj];
    }
    __syncthreads();

    int L0 = seq_lens[b0];
    int L1 = seq_lens[b1];
    int Lmax = max(L0, L1);

    const float* em0 = logit + (size_t)b0 * Tn * Kn;
    const float* em1 = logit + (size_t)b1 * Tn * Kn;
    float* avg0 = g_av + (size_t)b0 * Tn * Kn;
    float* avg1 = g_av + (size_t)b1 * Tn * Kn;

    float af0 = 0.f, av0 = 0.f, af1 = 0.f, av1 = 0.f;
    if (h == 0) {
        float sv = startv[j];
        af0 = sv + __ldcg(em0 + j); av0 = af0;
        af1 = sv + __ldcg(em1 + j); av1 = af1;
        __stcg(avg0 + j, av0);                 // av at t=0 (backtrace needs it)
        __stcg(avg1 + j, av1);
    }

    const float* Tb = s_T + (h * 64) * 128 + jl;   // this thread's T column walk

    for (int t = 1; t < Lmax; ++t) {
        int p = t & 1;
        bool act0 = t < L0, act1 = t < L1;

        float e0 = 0.f, e1 = 0.f;
        if (h == 0) {
            e0 = __ldcg(em0 + t * Kn + j);     // streaming: keep out of L1
            e1 = __ldcg(em1 + t * Kn + j);
            float4 st4 = make_float4(af0, av0, af1, av1);
            s_afav[p][j] = st4;                 // own half, local
            peer_afav[p * Kn + j] = st4;        // own half -> peer's smem
        }
        cl.sync();                               // exchange + full ordering

        // ---- stabilizer: m = alpha[0] (one broadcast; no reduction) ----
        float4 a0v = s_afav[p][0];
        float m0 = a0v.x, m1 = a0v.z;
        if (tid < 256) {
            float4 a = s_afav[p][tid];
            s_pva[tid] = make_float4(__expf(a.x - m0), a.y, __expf(a.z - m1), a.w);
        }
        __syncthreads();

        // ---- inner quarter-K: 64 rows, SMEM T + inline exp ----
        float s0 = 0.f, s1 = 0.f;
        float bv0 = -CUDART_INF_F, bv1 = -CUDART_INF_F;

        const float4* pv_ptr = s_pva + h * 64;

        #pragma unroll 16
        for (int i = 0; i < 64; ++i) {
            float tv = Tb[i * 128];              // conflict-free LDS.32
            float4 pv = pv_ptr[i];               // broadcast LDS.128
            float e = __expf(tv);                // == precomputed __expf(t)
            s0 += pv.x * e;
            s1 += pv.z * e;
            bv0 = fmaxf(bv0, pv.y + tv);         // exact fp32 add + exact max
            bv1 = fmaxf(bv1, pv.w + tv);
        }

        if (h) s_part[h - 1][jl] = make_float4(s0, s1, bv0, bv1);
        __syncthreads();

        if (h == 0) {
            #pragma unroll
            for (int q = 0; q < 3; ++q) {
                float4 ps = s_part[q][jl];
                s0 += ps.x;
                s1 += ps.y;
                bv0 = fmaxf(bv0, ps.z);
                bv1 = fmaxf(bv1, ps.w);
            }
            if (act0) {
                af0 = m0 + __logf(s0) + e0;
                av0 = bv0 + e0;
                __stcg(avg0 + t * Kn + j, av0);
            }
            if (act1) {
                af1 = m1 + __logf(s1) + e1;
                av1 = bv1 + e1;
                __stcg(avg1 + t * Kn + j, av1);
            }
        }
        // next step's cl.sync orders these updates vs peer reads
    }

    // ---- epilogue: exchange (af+end, av+end); rank 0 reduces ----
    int pe = Lmax & 1;
    if (h == 0) {
        float ev = endv[j];
        float4 st4 = make_float4(af0 + ev, av0 + ev, af1 + ev, av1 + ev);
        s_afav[pe][j] = st4;
        peer_afav[pe * Kn + j] = st4;
    }
    cl.sync();

    if (r == 0) {
        // logZ = logsumexp over 256 z-values, both batches (true max here)
        float z0 = 0.f, z1 = 0.f;
        if (tid < 256) {
            float4 a = s_afav[pe][tid];
            z0 = a.x; z1 = a.z;
            float x0 = z0, x1 = z1;
            #pragma unroll
            for (int o = 16; o; o >>= 1) {
                x0 = fmaxf(x0, __shfl_xor_sync(0xffffffffu, x0, o));
                x1 = fmaxf(x1, __shfl_xor_sync(0xffffffffu, x1, o));
            }
            if (lane == 0) { red0[w] = x0; red1[w] = x1; }
        }
        __syncthreads();
        float m0 = fmaxf(fmaxf(fmaxf(red0[0], red0[1]), fmaxf(red0[2], red0[3])),
                         fmaxf(fmaxf(red0[4], red0[5]), fmaxf(red0[6], red0[7])));
        float m1 = fmaxf(fmaxf(fmaxf(red1[0], red1[1]), fmaxf(red1[2], red1[3])),
                         fmaxf(fmaxf(red1[4], red1[5]), fmaxf(red1[6], red1[7])));
        __syncthreads();
        if (tid < 256) {
            float ex0 = __expf(z0 - m0);
            float ex1 = __expf(z1 - m1);
            #pragma unroll
            for (int o = 16; o; o >>= 1) {
                ex0 += __shfl_xor_sync(0xffffffffu, ex0, o);
                ex1 += __shfl_xor_sync(0xffffffffu, ex1, o);
            }
            if (lane == 0) { red0[w] = ex0; red1[w] = ex1; }
        }
        __syncthreads();
        if (tid == 0) {
            float ss0 = red0[0] + red0[1] + red0[2] + red0[3]
                      + red0[4] + red0[5] + red0[6] + red0[7];
            float ss1 = red1[0] + red1[1] + red1[2] + red1[3]
                      + red1[4] + red1[5] + red1[6] + red1[7];
            g_logZ[b0] = m0 + __logf(ss0);
            g_logZ[b1] = m1 + __logf(ss1);
            // best_last: first argmax, exact ascending linear scan
            float bv = s_afav[pe][0].y; int bi = 0;
            float bw = s_afav[pe][0].w; int bj = 0;
            for (int i = 1; i < Kn; ++i) {
                float v = s_afav[pe][i].y;
                float u = s_afav[pe][i].w;
                if (v > bv) { bv = v; bi = i; }
                if (u > bw) { bw = u; bj = i; }
            }
            g_best[b0] = bi;
            g_best[b1] = bj;
        }
    }
}

// ---------------- K2: gold-path score per batch ------------------------------
__global__ void k2_score(
    const float* __restrict__ logit,
    const float* __restrict__ trans,
    const float* __restrict__ startv,
    const float* __restrict__ endv,
    const int*   __restrict__ target,
    const int*   __restrict__ seq_lens)
{
    int b = blockIdx.x, tid = threadIdx.x;
    int L = seq_lens[b];
    const int*   tg = target + b * Tn;
    const float* em = logit + (size_t)b * Tn * Kn;

    float part = 0.f;
    for (int t = 1 + tid; t < L; t += blockDim.x) {
        int cur = tg[t], prev = tg[t - 1];
        part += trans[prev * Kn + cur] + em[t * Kn + cur];
    }
    #pragma unroll
    for (int o = 16; o; o >>= 1) part += __shfl_xor_sync(0xffffffffu, part, o);
    __shared__ float red[4];
    if ((tid & 31) == 0) red[tid >> 5] = part;
    __syncthreads();
    if (tid == 0) {
        float s = red[0] + red[1] + red[2] + red[3];
        int t0 = tg[0];
        s += startv[t0] + em[t0];
        s += endv[tg[L - 1]];
        g_score[b] = s;
    }
}

// ---------------- K3: loss = mean(logZ - score) ------------------------------
__global__ void k3_loss(float* __restrict__ out) {
    int b = threadIdx.x;  // 128 threads
    float v = g_logZ[b] - g_score[b];
    #pragma unroll
    for (int o = 16; o; o >>= 1) v += __shfl_xor_sync(0xffffffffu, v, o);
    __shared__ float red[4];
    if ((b & 31) == 0) red[b >> 5] = v;
    __syncthreads();
    if (b == 0) out[0] = (red[0] + red[1] + red[2] + red[3]) / (float)Bn;
}

// ---------------- K4: backtrace with on-the-fly backpointer recompute --------
// One warp per batch. bp[t][tag] = argmax_i(av[t-1][i] + trans[i][tag]) is
// recomputed exactly: same fp32 adds, first-index tie-break (per-lane
// ascending i with strict >, cross-lane min-index on equal values).
__global__ void k4_backtrace(const int* __restrict__ seq_lens,
                             float* __restrict__ out_pred)
{
    int b = blockIdx.x;
    int lane = threadIdx.x;
    int L = seq_lens[b];
    int tag = g_best[b];
    const float* avb = g_av + (size_t)b * Tn * Kn;

    if (lane == 0) {
        g_pred[b * Tn + Tn - 1] = tag;
        out_pred[b * Tn + Tn - 1] = (float)tag;
    }

    // prefetch av row for the first active step
    float avr[8];
    {
        const float* row = avb + (size_t)(min(L, Tn) - 2) * Kn;  // t-1 for t=L-1
        #pragma unroll
        for (int k = 0; k < 8; ++k) avr[k] = __ldcg(row + k * 32 + lane);
    }

    for (int s = Tn - 2; s >= 0; --s) {
        int t = s + 1;
        if (t < L) {
            const float* trow = g_transT + tag * Kn;
            float bv = -CUDART_INF_F; int bi = 0;
            #pragma unroll
            for (int k = 0; k < 8; ++k) {
                float v = avr[k] + __ldg(trow + k * 32 + lane);
                if (v > bv) { bv = v; bi = k * 32 + lane; }   // ascending i: first
            }
            // prefetch next av row (independent of the reduce below)
            if (t - 2 >= 0) {
                const float* row = avb + (size_t)(t - 2) * Kn;
                #pragma unroll
                for (int k = 0; k < 8; ++k) avr[k] = __ldcg(row + k * 32 + lane);
            }
            // cross-lane argmax, min-index tie-break
            #pragma unroll
            for (int o = 16; o; o >>= 1) {
                float ov = __shfl_xor_sync(0xffffffffu, bv, o);
                int   oi = __shfl_xor_sync(0xffffffffu, bi, o);
                if (ov > bv || (ov == bv && oi < bi)) { bv = ov; bi = oi; }
            }
            tag = bi;
        }
        if (lane == 0) {
            g_pred[b * Tn + s] = tag;
            out_pred[b * Tn + s] = (float)tag;
        }
    }
}

// ---------------- K5: rearrange + log_softmax --------------------------------
__global__ __launch_bounds__(Kn) void k5_logits(
    const float* __restrict__ logit,
    float* __restrict__ out_lp)
{
    int row = blockIdx.x;   // b*T + t
    int j = threadIdx.x;
    int lane = j & 31, w = j >> 5;

    const float* x = logit + (size_t)row * Kn;
    float xv = x[j];

    __shared__ float sh[Kn];
    __shared__ float redv[8];
    __shared__ int   redi[8];
    sh[j] = xv;

    // argmax with first-index tie-break (exact jnp.argmax semantics)
    float bv = xv; int bi = j;
    #pragma unroll
    for (int o = 16; o; o >>= 1) {
        float ov = __shfl_xor_sync(0xffffffffu, bv, o);
        int   oi = __shfl_xor_sync(0xffffffffu, bi, o);
        if (ov > bv || (ov == bv && oi < bi)) { bv = ov; bi = oi; }
    }
    if (lane == 0) { redv[w] = bv; redi[w] = bi; }
    __syncthreads();
    float mv = redv[0]; int mi = redi[0];
    #pragma unroll
    for (int k = 1; k < 8; ++k) {
        float ov = redv[k]; int oi = redi[k];
        if (ov > mv || (ov == mv && oi < mi)) { mv = ov; mi = oi; }
    }

    int p = g_pred[row];
    float labv = sh[p];

    float y = xv;
    if (j == p)  y = mv;     // out.at[pred].set(maxv)
    if (j == mi) y = labv;   // out.at[argm].set(labv)  (applied second, as in ref)

    // log_softmax: max of rearranged array == mv (value multiset preserved)
    float ex = __expf(y - mv);
    #pragma unroll
    for (int o = 16; o; o >>= 1) ex += __shfl_xor_sync(0xffffffffu, ex, o);
    __syncthreads();
    if (lane == 0) redv[w] = ex;
    __syncthreads();
    float ssum = redv[0] + redv[1] + redv[2] + redv[3]
               + redv[4] + redv[5] + redv[6] + redv[7];
    out_lp[(size_t)row * Kn + j] = y - mv - __logf(ssum);
}

// ---------------- launch ------------------------------------------------------
extern "C" void kernel_launch(void* const* d_in, const int* in_sizes, int n_in,
                              void* d_out, int out_size)
{
    (void)in_sizes; (void)n_in; (void)out_size;
    const float* logit  = (const float*)d_in[0];   // [B,T,K] f32
    const float* trans  = (const float*)d_in[1];   // [K,K]   f32
    const float* startv = (const float*)d_in[2];   // [K]     f32
    const float* endv   = (const float*)d_in[3];   // [K]     f32
    const int*   target = (const int*)d_in[4];     // [B,T]   i32
    const int*   seqlen = (const int*)d_in[5];     // [B]     i32

    float* out      = (float*)d_out;
    float* out_pred = out + 1;              // [B,T]   (pred cast to f32)
    float* out_lp   = out + 1 + Bn * Tn;    // [B,T,K]

    // allow 128 KB dynamic smem for the T slice (idempotent; not a stream op)
    cudaFuncSetAttribute(k1_scan, cudaFuncAttributeMaxDynamicSharedMemorySize,
                         Kn * 128 * (int)sizeof(float));

    k0_prep<<<(Kn * Kn + 255) / 256, 256>>>(trans);
    k1_scan<<<2 * HB, 512, Kn * 128 * sizeof(float)>>>(logit, trans, startv, endv, seqlen);
    k2_score<<<Bn, 128>>>(logit, trans, startv, endv, target, seqlen);
    k3_loss<<<1, 128>>>(out);
    k4_backtrace<<<Bn, 32>>>(seqlen, out_pred);
    k5_logits<<<Bn * Tn, Kn>>>(logit, out_lp);
}

// round 15
// speedup vs baseline: 1.3487x; 1.0516x over previous
#include <cuda_runtime.h>
#include <math_constants.h>
#include <cooperative_groups.h>

namespace cg = cooperative_groups;

#define Bn 128
#define Tn 512
#define Kn 256
#define HB 64   // clusters in k1; cluster c owns batches (c, c+HB)

// ---------------- scratch (static device globals; no allocation allowed) ----
__device__ float  g_transT[Kn * Kn];             // trans transposed: [j][i]
__device__ float  g_av[(size_t)Bn * Tn * Kn];    // Viterbi alphas (64 MiB)
__device__ float  g_logZ[Bn];
__device__ float  g_score[Bn];
__device__ int    g_best[Bn];
__device__ int    g_pred[Bn * Tn];

// ---------------- K0: transposed trans (for k4 backtrace) ---------------------
__global__ void k0_prep(const float* __restrict__ trans) {
    int idx = blockIdx.x * blockDim.x + threadIdx.x;
    if (idx < Kn * Kn) {
        int i = idx >> 8, j = idx & 255;
        g_transT[j * Kn + i] = trans[idx];
    }
}

// ---------------- K1: clustered forward(logZ) + Viterbi max scan --------------
// 2-CTA cluster per batch pair (b0=c, b1=c+HB). CTA rank r owns output columns
// j in [r*128, r*128+128). E = __expf(T) slice staged ONCE in 128KB dynamic
// SMEM (bit-identical to inline exp; zero MUFU in the hot loop); the exact
// fp32 T values live in per-thread registers (tr[32], fully unrolled).
// 1024 threads: thread (jl = tid&127, h = tid>>7) owns source rows
// [h*32, h*32+32). Stabilizer m = alpha[0]. One cluster.sync per step.
// No argmax in the hot loop; exact av stored to g_av for k4's recompute.
__global__ void __cluster_dims__(2, 1, 1) __launch_bounds__(1024, 1) k1_scan(
    const float* __restrict__ logit,
    const float* __restrict__ trans,
    const float* __restrict__ startv,
    const float* __restrict__ endv,
    const int*   __restrict__ seq_lens)
{
    cg::cluster_group cl = cg::this_cluster();
    const unsigned r = cl.block_rank();           // 0 or 1

    int cid = blockIdx.x >> 1;
    int b0 = cid, b1 = cid + HB;
    int tid = threadIdx.x;
    int jl = tid & 127;
    int h = tid >> 7;                             // 0..7, owns 32 rows
    int j = (int)r * 128 + jl;                    // global output column
    int lane = tid & 31, w = tid >> 5;            // warps 0..31

    extern __shared__ float s_E[];     // [256 rows][128 cols] = 128 KB: exp(T) slice

    __shared__ float4 s_afav[2][Kn];   // parity-buffered (af0, av0, af1, av1), all i
    __shared__ float4 s_pva[Kn];       // (p0, av0, p1, av1), all i
    __shared__ float4 s_part[7][128];  // h=1..7 partials (s0, s1, bv0, bv1)
    __shared__ float  red0[8], red1[8];

    float4* peer_afav = (float4*)cl.map_shared_rank(&s_afav[0][0], r ^ 1);

    // ---- one-time: stage E = __expf(T) slice into smem (coalesced) ----
    for (int idx = tid; idx < Kn * 128; idx += 1024) {
        int i = idx >> 7, jj = idx & 127;
        s_E[idx] = __expf(trans[i * Kn + (int)r * 128 + jj]);
    }

    // ---- exact T values for this thread's 32 rows -> registers ----
    float tr[32];
    #pragma unroll
    for (int i = 0; i < 32; ++i)
        tr[i] = __ldg(trans + (size_t)(h * 32 + i) * Kn + j);
    __syncthreads();

    int L0 = seq_lens[b0];
    int L1 = seq_lens[b1];
    int Lmax = max(L0, L1);

    const float* em0 = logit + (size_t)b0 * Tn * Kn;
    const float* em1 = logit + (size_t)b1 * Tn * Kn;
    float* avg0 = g_av + (size_t)b0 * Tn * Kn;
    float* avg1 = g_av + (size_t)b1 * Tn * Kn;

    float af0 = 0.f, av0 = 0.f, af1 = 0.f, av1 = 0.f;
    if (h == 0) {
        float sv = startv[j];
        af0 = sv + __ldcg(em0 + j); av0 = af0;
        af1 = sv + __ldcg(em1 + j); av1 = af1;
        __stcg(avg0 + j, av0);                 // av at t=0 (backtrace needs it)
        __stcg(avg1 + j, av1);
    }

    const float* Eb = s_E + (h * 32) * 128 + jl;   // this thread's E column walk

    for (int t = 1; t < Lmax; ++t) {
        int p = t & 1;
        bool act0 = t < L0, act1 = t < L1;

        float e0 = 0.f, e1 = 0.f;
        if (h == 0) {
            e0 = __ldcg(em0 + t * Kn + j);     // streaming: keep out of L1
            e1 = __ldcg(em1 + t * Kn + j);
            float4 st4 = make_float4(af0, av0, af1, av1);
            s_afav[p][j] = st4;                 // own half, local
            peer_afav[p * Kn + j] = st4;        // own half -> peer's smem
        }
        cl.sync();                               // exchange + full ordering

        // ---- stabilizer: m = alpha[0] (one broadcast; no reduction) ----
        float4 a0v = s_afav[p][0];
        float m0 = a0v.x, m1 = a0v.z;
        if (tid < 256) {
            float4 a = s_afav[p][tid];
            s_pva[tid] = make_float4(__expf(a.x - m0), a.y, __expf(a.z - m1), a.w);
        }
        __syncthreads();

        // ---- inner 1/8-K: 32 rows, SMEM E + register T, zero MUFU ----
        float s0 = 0.f, s1 = 0.f;
        float bv0 = -CUDART_INF_F, bv1 = -CUDART_INF_F;

        const float4* pv_ptr = s_pva + h * 32;

        #pragma unroll
        for (int i = 0; i < 32; ++i) {
            float e = Eb[i * 128];               // conflict-free LDS.32
            float tv = tr[i];                    // exact T from register
            float4 pv = pv_ptr[i];               // broadcast LDS.128
            s0 += pv.x * e;
            s1 += pv.z * e;
            bv0 = fmaxf(bv0, pv.y + tv);         // exact fp32 add + exact max
            bv1 = fmaxf(bv1, pv.w + tv);
        }

        if (h) s_part[h - 1][jl] = make_float4(s0, s1, bv0, bv1);
        __syncthreads();

        if (h == 0) {
            #pragma unroll
            for (int q = 0; q < 7; ++q) {
                float4 ps = s_part[q][jl];
                s0 += ps.x;
                s1 += ps.y;
                bv0 = fmaxf(bv0, ps.z);
                bv1 = fmaxf(bv1, ps.w);
            }
            if (act0) {
                af0 = m0 + __logf(s0) + e0;
                av0 = bv0 + e0;
                __stcg(avg0 + t * Kn + j, av0);
            }
            if (act1) {
                af1 = m1 + __logf(s1) + e1;
                av1 = bv1 + e1;
                __stcg(avg1 + t * Kn + j, av1);
            }
        }
        // next step's cl.sync orders these updates vs peer reads
    }

    // ---- epilogue: exchange (af+end, av+end); rank 0 reduces ----
    int pe = Lmax & 1;
    if (h == 0) {
        float ev = endv[j];
        float4 st4 = make_float4(af0 + ev, av0 + ev, af1 + ev, av1 + ev);
        s_afav[pe][j] = st4;
        peer_afav[pe * Kn + j] = st4;
    }
    cl.sync();

    if (r == 0) {
        // logZ = logsumexp over 256 z-values, both batches (true max here)
        float z0 = 0.f, z1 = 0.f;
        if (tid < 256) {
            float4 a = s_afav[pe][tid];
            z0 = a.x; z1 = a.z;
            float x0 = z0, x1 = z1;
            #pragma unroll
            for (int o = 16; o; o >>= 1) {
                x0 = fmaxf(x0, __shfl_xor_sync(0xffffffffu, x0, o));
                x1 = fmaxf(x1, __shfl_xor_sync(0xffffffffu, x1, o));
            }
            if (lane == 0) { red0[w] = x0; red1[w] = x1; }
        }
        __syncthreads();
        float m0 = fmaxf(fmaxf(fmaxf(red0[0], red0[1]), fmaxf(red0[2], red0[3])),
                         fmaxf(fmaxf(red0[4], red0[5]), fmaxf(red0[6], red0[7])));
        float m1 = fmaxf(fmaxf(fmaxf(red1[0], red1[1]), fmaxf(red1[2], red1[3])),
                         fmaxf(fmaxf(red1[4], red1[5]), fmaxf(red1[6], red1[7])));
        __syncthreads();
        if (tid < 256) {
            float ex0 = __expf(z0 - m0);
            float ex1 = __expf(z1 - m1);
            #pragma unroll
            for (int o = 16; o; o >>= 1) {
                ex0 += __shfl_xor_sync(0xffffffffu, ex0, o);
                ex1 += __shfl_xor_sync(0xffffffffu, ex1, o);
            }
            if (lane == 0) { red0[w] = ex0; red1[w] = ex1; }
        }
        __syncthreads();
        if (tid == 0) {
            float ss0 = red0[0] + red0[1] + red0[2] + red0[3]
                      + red0[4] + red0[5] + red0[6] + red0[7];
            float ss1 = red1[0] + red1[1] + red1[2] + red1[3]
                      + red1[4] + red1[5] + red1[6] + red1[7];
            g_logZ[b0] = m0 + __logf(ss0);
            g_logZ[b1] = m1 + __logf(ss1);
            // best_last: first argmax, exact ascending linear scan
            float bv = s_afav[pe][0].y; int bi = 0;
            float bw = s_afav[pe][0].w; int bj = 0;
            for (int i = 1; i < Kn; ++i) {
                float v = s_afav[pe][i].y;
                float u = s_afav[pe][i].w;
                if (v > bv) { bv = v; bi = i; }
                if (u > bw) { bw = u; bj = i; }
            }
            g_best[b0] = bi;
            g_best[b1] = bj;
        }
    }
}

// ---------------- K2: gold-path score per batch ------------------------------
__global__ void k2_score(
    const float* __restrict__ logit,
    const float* __restrict__ trans,
    const float* __restrict__ startv,
    const float* __restrict__ endv,
    const int*   __restrict__ target,
    const int*   __restrict__ seq_lens)
{
    int b = blockIdx.x, tid = threadIdx.x;
    int L = seq_lens[b];
    const int*   tg = target + b * Tn;
    const float* em = logit + (size_t)b * Tn * Kn;

    float part = 0.f;
    for (int t = 1 + tid; t < L; t += blockDim.x) {
        int cur = tg[t], prev = tg[t - 1];
        part += trans[prev * Kn + cur] + em[t * Kn + cur];
    }
    #pragma unroll
    for (int o = 16; o; o >>= 1) part += __shfl_xor_sync(0xffffffffu, part, o);
    __shared__ float red[4];
    if ((tid & 31) == 0) red[tid >> 5] = part;
    __syncthreads();
    if (tid == 0) {
        float s = red[0] + red[1] + red[2] + red[3];
        int t0 = tg[0];
        s += startv[t0] + em[t0];
        s += endv[tg[L - 1]];
        g_score[b] = s;
    }
}

// ---------------- K3: loss = mean(logZ - score) ------------------------------
__global__ void k3_loss(float* __restrict__ out) {
    int b = threadIdx.x;  // 128 threads
    float v = g_logZ[b] - g_score[b];
    #pragma unroll
    for (int o = 16; o; o >>= 1) v += __shfl_xor_sync(0xffffffffu, v, o);
    __shared__ float red[4];
    if ((b & 31) == 0) red[b >> 5] = v;
    __syncthreads();
    if (b == 0) out[0] = (red[0] + red[1] + red[2] + red[3]) / (float)Bn;
}

// ---------------- K4: backtrace with on-the-fly backpointer recompute --------
// One warp per batch. bp[t][tag] = argmax_i(av[t-1][i] + trans[i][tag]) is
// recomputed exactly: same fp32 adds, first-index tie-break (per-lane
// ascending i with strict >, cross-lane min-index on equal values).
__global__ void k4_backtrace(const int* __restrict__ seq_lens,
                             float* __restrict__ out_pred)
{
    int b = blockIdx.x;
    int lane = threadIdx.x;
    int L = seq_lens[b];
    int tag = g_best[b];
    const float* avb = g_av + (size_t)b * Tn * Kn;

    if (lane == 0) {
        g_pred[b * Tn + Tn - 1] = tag;
        out_pred[b * Tn + Tn - 1] = (float)tag;
    }

    // prefetch av row for the first active step
    float avr[8];
    {
        const float* row = avb + (size_t)(min(L, Tn) - 2) * Kn;  // t-1 for t=L-1
        #pragma unroll
        for (int k = 0; k < 8; ++k) avr[k] = __ldcg(row + k * 32 + lane);
    }

    for (int s = Tn - 2; s >= 0; --s) {
        int t = s + 1;
        if (t < L) {
            const float* trow = g_transT + tag * Kn;
            float bv = -CUDART_INF_F; int bi = 0;
            #pragma unroll
            for (int k = 0; k < 8; ++k) {
                float v = avr[k] + __ldg(trow + k * 32 + lane);
                if (v > bv) { bv = v; bi = k * 32 + lane; }   // ascending i: first
            }
            // prefetch next av row (independent of the reduce below)
            if (t - 2 >= 0) {
                const float* row = avb + (size_t)(t - 2) * Kn;
                #pragma unroll
                for (int k = 0; k < 8; ++k) avr[k] = __ldcg(row + k * 32 + lane);
            }
            // cross-lane argmax, min-index tie-break
            #pragma unroll
            for (int o = 16; o; o >>= 1) {
                float ov = __shfl_xor_sync(0xffffffffu, bv, o);
                int   oi = __shfl_xor_sync(0xffffffffu, bi, o);
                if (ov > bv || (ov == bv && oi < bi)) { bv = ov; bi = oi; }
            }
            tag = bi;
        }
        if (lane == 0) {
            g_pred[b * Tn + s] = tag;
            out_pred[b * Tn + s] = (float)tag;
        }
    }
}

// ---------------- K5: rearrange + log_softmax --------------------------------
__global__ __launch_bounds__(Kn) void k5_logits(
    const float* __restrict__ logit,
    float* __restrict__ out_lp)
{
    int row = blockIdx.x;   // b*T + t
    int j = threadIdx.x;
    int lane = j & 31, w = j >> 5;

    const float* x = logit + (size_t)row * Kn;
    float xv = x[j];

    __shared__ float sh[Kn];
    __shared__ float redv[8];
    __shared__ int   redi[8];
    sh[j] = xv;

    // argmax with first-index tie-break (exact jnp.argmax semantics)
    float bv = xv; int bi = j;
    #pragma unroll
    for (int o = 16; o; o >>= 1) {
        float ov = __shfl_xor_sync(0xffffffffu, bv, o);
        int   oi = __shfl_xor_sync(0xffffffffu, bi, o);
        if (ov > bv || (ov == bv && oi < bi)) { bv = ov; bi = oi; }
    }
    if (lane == 0) { redv[w] = bv; redi[w] = bi; }
    __syncthreads();
    float mv = redv[0]; int mi = redi[0];
    #pragma unroll
    for (int k = 1; k < 8; ++k) {
        float ov = redv[k]; int oi = redi[k];
        if (ov > mv || (ov == mv && oi < mi)) { mv = ov; mi = oi; }
    }

    int p = g_pred[row];
    float labv = sh[p];

    float y = xv;
    if (j == p)  y = mv;     // out.at[pred].set(maxv)
    if (j == mi) y = labv;   // out.at[argm].set(labv)  (applied second, as in ref)

    // log_softmax: max of rearranged array == mv (value multiset preserved)
    float ex = __expf(y - mv);
    #pragma unroll
    for (int o = 16; o; o >>= 1) ex += __shfl_xor_sync(0xffffffffu, ex, o);
    __syncthreads();
    if (lane == 0) redv[w] = ex;
    __syncthreads();
    float ssum = redv[0] + redv[1] + redv[2] + redv[3]
               + redv[4] + redv[5] + redv[6] + redv[7];
    out_lp[(size_t)row * Kn + j] = y - mv - __logf(ssum);
}

// ---------------- launch ------------------------------------------------------
extern "C" void kernel_launch(void* const* d_in, const int* in_sizes, int n_in,
                              void* d_out, int out_size)
{
    (void)in_sizes; (void)n_in; (void)out_size;
    const float* logit  = (const float*)d_in[0];   // [B,T,K] f32
    const float* trans  = (const float*)d_in[1];   // [K,K]   f32
    const float* startv = (const float*)d_in[2];   // [K]     f32
    const float* endv   = (const float*)d_in[3];   // [K]     f32
    const int*   target = (const int*)d_in[4];     // [B,T]   i32
    const int*   seqlen = (const int*)d_in[5];     // [B]     i32

    float* out      = (float*)d_out;
    float* out_pred = out + 1;              // [B,T]   (pred cast to f32)
    float* out_lp   = out + 1 + Bn * Tn;    // [B,T,K]

    // allow 128 KB dynamic smem for the E slice (idempotent; not a stream op)
    cudaFuncSetAttribute(k1_scan, cudaFuncAttributeMaxDynamicSharedMemorySize,
                         Kn * 128 * (int)sizeof(float));

    k0_prep<<<(Kn * Kn + 255) / 256, 256>>>(trans);
    k1_scan<<<2 * HB, 1024, Kn * 128 * sizeof(float)>>>(logit, trans, startv, endv, seqlen);
    k2_score<<<Bn, 128>>>(logit, trans, startv, endv, target, seqlen);
    k3_loss<<<1, 128>>>(out);
    k4_backtrace<<<Bn, 32>>>(seqlen, out_pred);
    k5_logits<<<Bn * Tn, Kn>>>(logit, out_lp);
}